// round 3
// baseline (speedup 1.0000x reference)
#include <cuda_runtime.h>

// Problem constants
#define Dm    1024          // sent_dim (= N of both GEMMs, = K of main GEMM)
#define LDW   2048          // W1_w row stride (2*D)
#define Bsz   8
#define Lw    4096          // words per sample (power of 2; b = row >> 12)
#define Ssent 255
#define MS    (Bsz * Ssent) // 2040 rows of the sentence pre-GEMM

// Tiling
#define BM 128
#define BN 128
#define BK 8

// Scratch: Y2[b, s, d] = sents_emb[b,s,:] @ W1_w[:, 1024:2048]^T
__device__ float g_Y2[Bsz * Ssent * Dm];

// ---------------------------------------------------------------------------
// Kernel A: Y2[m', n] = sum_k sents[m', k] * Wb[n, k],  m' in [0, 2040)
//   sents: [2040 x 1024] row-major (B*S rows contiguous)
//   Wb   : W1_w + 1024, row-major [1024 x 2048] (ld = 2048)
// ---------------------------------------------------------------------------
__global__ __launch_bounds__(256, 2)
void sent_gemm_kernel(const float* __restrict__ A,
                      const float* __restrict__ W)
{
    __shared__ float As[2][BK][BM];
    __shared__ float Bs[2][BK][BN];

    const int tid      = threadIdx.x;
    const int rowStart = blockIdx.x * BM;
    const int colStart = blockIdx.y * BN;

    const int loadRow = tid >> 1;          // 0..127
    const int loadCol = (tid & 1) << 2;    // 0 or 4

    int aRowG = rowStart + loadRow;
    int aRowC = (aRowG < MS) ? aRowG : (MS - 1);     // clamp; store is guarded
    const float* aPtr = A + (size_t)aRowC * Dm + loadCol;
    const float* bPtr = W + (size_t)(colStart + loadRow) * LDW + loadCol;

    const int tx = tid & 15;
    const int ty = tid >> 4;

    float acc[8][8];
    #pragma unroll
    for (int i = 0; i < 8; ++i)
        #pragma unroll
        for (int j = 0; j < 8; ++j) acc[i][j] = 0.f;

    // prologue: stage 0
    {
        float4 a = *(const float4*)(aPtr);
        float4 b = *(const float4*)(bPtr);
        As[0][loadCol + 0][loadRow] = a.x;
        As[0][loadCol + 1][loadRow] = a.y;
        As[0][loadCol + 2][loadRow] = a.z;
        As[0][loadCol + 3][loadRow] = a.w;
        Bs[0][loadCol + 0][loadRow] = b.x;
        Bs[0][loadCol + 1][loadRow] = b.y;
        Bs[0][loadCol + 2][loadRow] = b.z;
        Bs[0][loadCol + 3][loadRow] = b.w;
    }
    __syncthreads();

    const int steps = Dm / BK;   // 128
    float af[8], bf[8];

    for (int t = 0; t < steps; ++t) {
        const int buf = t & 1;
        float4 aN, bN;
        if (t + 1 < steps) {
            aN = *(const float4*)(aPtr + (t + 1) * BK);
            bN = *(const float4*)(bPtr + (t + 1) * BK);
        }
        #pragma unroll
        for (int k = 0; k < BK; ++k) {
            *(float4*)&af[0] = *(const float4*)&As[buf][k][ty * 4];
            *(float4*)&af[4] = *(const float4*)&As[buf][k][64 + ty * 4];
            *(float4*)&bf[0] = *(const float4*)&Bs[buf][k][tx * 4];
            *(float4*)&bf[4] = *(const float4*)&Bs[buf][k][64 + tx * 4];
            #pragma unroll
            for (int i = 0; i < 8; ++i)
                #pragma unroll
                for (int j = 0; j < 8; ++j)
                    acc[i][j] = fmaf(af[i], bf[j], acc[i][j]);
        }
        if (t + 1 < steps) {
            const int nb = buf ^ 1;
            As[nb][loadCol + 0][loadRow] = aN.x;
            As[nb][loadCol + 1][loadRow] = aN.y;
            As[nb][loadCol + 2][loadRow] = aN.z;
            As[nb][loadCol + 3][loadRow] = aN.w;
            Bs[nb][loadCol + 0][loadRow] = bN.x;
            Bs[nb][loadCol + 1][loadRow] = bN.y;
            Bs[nb][loadCol + 2][loadRow] = bN.z;
            Bs[nb][loadCol + 3][loadRow] = bN.w;
            __syncthreads();
        }
    }

    // epilogue: raw store into Y2 (guarded on rows)
    #pragma unroll
    for (int i = 0; i < 8; ++i) {
        int r = rowStart + ((i < 4) ? (ty * 4 + i) : (64 + ty * 4 + (i - 4)));
        if (r < MS) {
            float* yp = g_Y2 + (size_t)r * Dm + colStart;
            float4 v0 = make_float4(acc[i][0], acc[i][1], acc[i][2], acc[i][3]);
            float4 v1 = make_float4(acc[i][4], acc[i][5], acc[i][6], acc[i][7]);
            *(float4*)(yp + tx * 4)      = v0;
            *(float4*)(yp + 64 + tx * 4) = v1;
        }
    }
}

// ---------------------------------------------------------------------------
// Kernel B: out[m, n] = relu( words[m,:] @ Wa[n,:] + bias[n]
//                             + (smap[m] >= 0 ? Y2[b, smap[m], n] : 0) )
//   words: [32768 x 1024], Wa = W1_w (ld 2048), b = m >> 12
// ---------------------------------------------------------------------------
__global__ __launch_bounds__(256, 2)
void main_gemm_kernel(const float* __restrict__ A,
                      const float* __restrict__ W,
                      const float* __restrict__ bias,
                      const int*   __restrict__ smap,
                      float* __restrict__ out)
{
    __shared__ float As[2][BK][BM];
    __shared__ float Bs[2][BK][BN];

    const int tid      = threadIdx.x;
    const int rowStart = blockIdx.x * BM;
    const int colStart = blockIdx.y * BN;

    const int loadRow = tid >> 1;
    const int loadCol = (tid & 1) << 2;

    const float* aPtr = A + (size_t)(rowStart + loadRow) * Dm + loadCol;
    const float* bPtr = W + (size_t)(colStart + loadRow) * LDW + loadCol;

    const int tx = tid & 15;
    const int ty = tid >> 4;

    float acc[8][8];
    #pragma unroll
    for (int i = 0; i < 8; ++i)
        #pragma unroll
        for (int j = 0; j < 8; ++j) acc[i][j] = 0.f;

    {
        float4 a = *(const float4*)(aPtr);
        float4 b = *(const float4*)(bPtr);
        As[0][loadCol + 0][loadRow] = a.x;
        As[0][loadCol + 1][loadRow] = a.y;
        As[0][loadCol + 2][loadRow] = a.z;
        As[0][loadCol + 3][loadRow] = a.w;
        Bs[0][loadCol + 0][loadRow] = b.x;
        Bs[0][loadCol + 1][loadRow] = b.y;
        Bs[0][loadCol + 2][loadRow] = b.z;
        Bs[0][loadCol + 3][loadRow] = b.w;
    }
    __syncthreads();

    const int steps = Dm / BK;   // 128
    float af[8], bf[8];

    for (int t = 0; t < steps; ++t) {
        const int buf = t & 1;
        float4 aN, bN;
        if (t + 1 < steps) {
            aN = *(const float4*)(aPtr + (t + 1) * BK);
            bN = *(const float4*)(bPtr + (t + 1) * BK);
        }
        #pragma unroll
        for (int k = 0; k < BK; ++k) {
            *(float4*)&af[0] = *(const float4*)&As[buf][k][ty * 4];
            *(float4*)&af[4] = *(const float4*)&As[buf][k][64 + ty * 4];
            *(float4*)&bf[0] = *(const float4*)&Bs[buf][k][tx * 4];
            *(float4*)&bf[4] = *(const float4*)&Bs[buf][k][64 + tx * 4];
            #pragma unroll
            for (int i = 0; i < 8; ++i)
                #pragma unroll
                for (int j = 0; j < 8; ++j)
                    acc[i][j] = fmaf(af[i], bf[j], acc[i][j]);
        }
        if (t + 1 < steps) {
            const int nb = buf ^ 1;
            As[nb][loadCol + 0][loadRow] = aN.x;
            As[nb][loadCol + 1][loadRow] = aN.y;
            As[nb][loadCol + 2][loadRow] = aN.z;
            As[nb][loadCol + 3][loadRow] = aN.w;
            Bs[nb][loadCol + 0][loadRow] = bN.x;
            Bs[nb][loadCol + 1][loadRow] = bN.y;
            Bs[nb][loadCol + 2][loadRow] = bN.z;
            Bs[nb][loadCol + 3][loadRow] = bN.w;
            __syncthreads();
        }
    }

    // epilogue: bias + gathered sentence projection + ReLU
    const int b = rowStart >> 12;                           // Lw = 4096
    const float* y2base = g_Y2 + (size_t)b * Ssent * Dm + colStart;
    const float4 bias0 = *(const float4*)(bias + colStart + tx * 4);
    const float4 bias1 = *(const float4*)(bias + colStart + 64 + tx * 4);

    #pragma unroll
    for (int i = 0; i < 8; ++i) {
        const int r  = rowStart + ((i < 4) ? (ty * 4 + i) : (64 + ty * 4 + (i - 4)));
        const int sv = smap[r];
        float4 y0 = make_float4(0.f, 0.f, 0.f, 0.f);
        float4 y1 = y0;
        if (sv >= 0) {
            const float* yp = y2base + (size_t)sv * Dm;
            y0 = *(const float4*)(yp + tx * 4);
            y1 = *(const float4*)(yp + 64 + tx * 4);
        }
        float4 o0, o1;
        o0.x = fmaxf(acc[i][0] + bias0.x + y0.x, 0.f);
        o0.y = fmaxf(acc[i][1] + bias0.y + y0.y, 0.f);
        o0.z = fmaxf(acc[i][2] + bias0.z + y0.z, 0.f);
        o0.w = fmaxf(acc[i][3] + bias0.w + y0.w, 0.f);
        o1.x = fmaxf(acc[i][4] + bias1.x + y1.x, 0.f);
        o1.y = fmaxf(acc[i][5] + bias1.y + y1.y, 0.f);
        o1.z = fmaxf(acc[i][6] + bias1.z + y1.z, 0.f);
        o1.w = fmaxf(acc[i][7] + bias1.w + y1.w, 0.f);
        float* op = out + (size_t)r * Dm + colStart;
        *(float4*)(op + tx * 4)      = o0;
        *(float4*)(op + 64 + tx * 4) = o1;
    }
}

// ---------------------------------------------------------------------------
extern "C" void kernel_launch(void* const* d_in, const int* in_sizes, int n_in,
                              void* d_out, int out_size)
{
    const float* words = (const float*)d_in[0];  // [8, 4096, 1024] f32
    const float* sents = (const float*)d_in[1];  // [8, 255, 1024]  f32
    const float* W1w   = (const float*)d_in[2];  // [1024, 2048]    f32
    const float* W1b   = (const float*)d_in[3];  // [1024]          f32
    const int*   smap  = (const int*)d_in[4];    // [8, 4096]       i32
    float*       out   = (float*)d_out;          // [8, 4096, 1024] f32

    // Kernel A: sentence pre-projection into g_Y2 (second half of W's K dim)
    dim3 gridA((MS + BM - 1) / BM, Dm / BN);     // 16 x 8
    sent_gemm_kernel<<<gridA, 256>>>(sents, W1w + Dm);

    // Kernel B: main GEMM over first half of K, fused gather/bias/relu epilogue
    dim3 gridB((Bsz * Lw) / BM, Dm / BN);        // 256 x 8
    main_gemm_kernel<<<gridB, 256>>>(words, W1w, W1b, smap, out);
}

// round 6
// speedup vs baseline: 1.8855x; 1.8855x over previous
#include <cuda_runtime.h>
#include <cuda_bf16.h>
#include <cstdint>

// ---------------------------------------------------------------- constants
#define Dm     1024
#define LDW    2048
#define Bsz    8
#define Lw     4096
#define Ssent  255

#define BM     128
#define BN     128
#define BK     32            // bf16 k per chunk
#define KCH    96            // 3 segments * 1024 / 32
#define STAGES 3
#define ROWB   80            // smem row stride bytes (32 bf16 + 16B pad)
#define STG_B  (128 * ROWB)  // 10240 per matrix per stage
#define SMEM_SZ (2 * STAGES * STG_B)   // 61440

// ---------------------------------------------------------------- scratch
__device__ __nv_bfloat16 g_Aw[32768ull * 2048];  // words  [hi | lo]
__device__ __nv_bfloat16 g_Wa[1024ull  * 2048];  // W[:, :1024] [hi | lo]
__device__ __nv_bfloat16 g_Wb[1024ull  * 2048];  // W[:, 1024:] [hi | lo]
__device__ __nv_bfloat16 g_Sp[2048ull  * 2048];  // sents padded (rows>=2040 zero)
__device__ float         g_Y2[2048ull  * 1024];  // sentence pre-projection

// ---------------------------------------------------------------- PTX utils
__device__ __forceinline__ uint32_t smem_u32(const void* p) {
    uint32_t a;
    asm("{ .reg .u64 t; cvta.to.shared.u64 t, %1; cvt.u32.u64 %0, t; }"
        : "=r"(a) : "l"(p));
    return a;
}
__device__ __forceinline__ void cp16(uint32_t dst, const void* src) {
    asm volatile("cp.async.cg.shared.global [%0], [%1], 16;"
                 :: "r"(dst), "l"(src));
}
#define CP_COMMIT() asm volatile("cp.async.commit_group;" ::: "memory")
#define CP_WAIT(n)  asm volatile("cp.async.wait_group %0;" :: "n"(n) : "memory")

// non-trans ldmatrix: for operands stored with contiguous k per row
// (A: rows=m, B: rows=n). mma's b0 needs {B[k][n],B[k+1][n]} = contiguous k. ✓
#define LDSM_X4(r, addr) \
    asm volatile("ldmatrix.sync.aligned.m8n8.x4.shared.b16 {%0,%1,%2,%3}, [%4];" \
        : "=r"((r)[0]), "=r"((r)[1]), "=r"((r)[2]), "=r"((r)[3]) : "r"(addr))

__device__ __forceinline__ void mma16816(float* c, const uint32_t* a,
                                         uint32_t b0, uint32_t b1) {
    asm volatile(
        "mma.sync.aligned.m16n8k16.row.col.f32.bf16.bf16.f32 "
        "{%0,%1,%2,%3}, {%4,%5,%6,%7}, {%8,%9}, {%0,%1,%2,%3};"
        : "+f"(c[0]), "+f"(c[1]), "+f"(c[2]), "+f"(c[3])
        : "r"(a[0]), "r"(a[1]), "r"(a[2]), "r"(a[3]), "r"(b0), "r"(b1));
}

// ---------------------------------------------------------------- split kernel
__global__ __launch_bounds__(256)
void split_kernel(const float* __restrict__ src, int srcPitch, int srcOfs,
                  __nv_bfloat16* __restrict__ dst)
{
    const int r = blockIdx.x;
    const int c = threadIdx.x * 4;
    float4 v = *(const float4*)(src + (size_t)r * srcPitch + srcOfs + c);

    __nv_bfloat16 h0 = __float2bfloat16(v.x);
    __nv_bfloat16 h1 = __float2bfloat16(v.y);
    __nv_bfloat16 h2 = __float2bfloat16(v.z);
    __nv_bfloat16 h3 = __float2bfloat16(v.w);
    __nv_bfloat16 l0 = __float2bfloat16(v.x - __bfloat162float(h0));
    __nv_bfloat16 l1 = __float2bfloat16(v.y - __bfloat162float(h1));
    __nv_bfloat16 l2 = __float2bfloat16(v.z - __bfloat162float(h2));
    __nv_bfloat16 l3 = __float2bfloat16(v.w - __bfloat162float(h3));

    __nv_bfloat162 hp0{h0, h1}, hp1{h2, h3}, lp0{l0, l1}, lp1{l2, l3};
    uint2 hw, lw;
    hw.x = *(uint32_t*)&hp0; hw.y = *(uint32_t*)&hp1;
    lw.x = *(uint32_t*)&lp0; lw.y = *(uint32_t*)&lp1;
    *(uint2*)(dst + (size_t)r * 2048 + c)        = hw;
    *(uint2*)(dst + (size_t)r * 2048 + 1024 + c) = lw;
}

// ---------------------------------------------------------------- GEMM kernel
// out[m,n] = sum over 3 bf16 segments (hi.hi, lo.hi, hi.lo) of A'[m,:] . B'[n,:]
// FUSED: + bias + gather(Y2 via smap) + ReLU
template<bool FUSED>
__global__ __launch_bounds__(256, 2)
void gemm_bf16x3(const __nv_bfloat16* __restrict__ Ap,
                 const __nv_bfloat16* __restrict__ Bp,
                 const float* __restrict__ bias,
                 const int*   __restrict__ smap,
                 const float* __restrict__ y2,
                 float* __restrict__ out)
{
    extern __shared__ char smem_raw[];
    const uint32_t aBase = smem_u32(smem_raw);
    const uint32_t bBase = aBase + STAGES * STG_B;

    const int tid  = threadIdx.x;
    const int lane = tid & 31;
    const int wid  = tid >> 5;
    const int wm   = wid >> 1;         // 0..3 -> M offset wm*32
    const int wn   = wid & 1;          // 0..1 -> N offset wn*64
    const int nStart = blockIdx.x * BN;    // N fastest: A block reused via L2
    const int mStart = blockIdx.y * BM;

    // ---- cp.async prefetch of one k-chunk (32 bf16 wide) for A and B
    auto prefetch = [&](int u) {
        const int seg = u >> 5, w = u & 31;
        const int kA = ((seg == 1) ? 1024 : 0) + w * BK;   // seg0/2: hi, seg1: lo
        const int kB = ((seg == 2) ? 1024 : 0) + w * BK;   // seg0/1: hi, seg2: lo
        const uint32_t sa = aBase + (u % STAGES) * STG_B;
        const uint32_t sb = bBase + (u % STAGES) * STG_B;
        #pragma unroll
        for (int i = 0; i < 2; i++) {                      // A: 512 16B tasks
            const int idx = tid + i * 256;
            const int row = idx >> 2, ch = idx & 3;
            cp16(sa + row * ROWB + ch * 16,
                 Ap + (size_t)(mStart + row) * 2048 + kA + ch * 8);
        }
        #pragma unroll
        for (int i = 0; i < 2; i++) {                      // B: 512 16B tasks
            const int idx = tid + i * 256;
            const int row = idx >> 2, ch = idx & 3;
            cp16(sb + row * ROWB + ch * 16,
                 Bp + (size_t)(nStart + row) * 2048 + kB + ch * 8);
        }
        CP_COMMIT();
    };

    prefetch(0);
    prefetch(1);

    float acc[2][8][4];
    #pragma unroll
    for (int mt = 0; mt < 2; mt++)
        #pragma unroll
        for (int nt = 0; nt < 8; nt++)
            #pragma unroll
            for (int j = 0; j < 4; j++) acc[mt][nt][j] = 0.f;

    // per-lane ldmatrix address offsets (within a stage)
    // A x4: lanes 0-7 -> m0-7 k0 (a0) | 8-15 -> m8-15 k0 (a1)
    //       | 16-23 -> m0-7 k8 (a2) | 24-31 -> m8-15 k8 (a3)
    const uint32_t aOff = (uint32_t)(wm * 32 + (lane & 15)) * ROWB
                        + ((lane >> 4) * 16);
    // B x4: lanes 0-7 -> n0-7 k0 (b0) | 8-15 -> n0-7 k8 (b1)
    //       | 16-23 -> n8-15 k0 (b0') | 24-31 -> n8-15 k8 (b1')
    const uint32_t bOff = (uint32_t)(wn * 64 + ((lane >> 4) & 1) * 8 + (lane & 7)) * ROWB
                        + (((lane >> 3) & 1) * 16);

    for (int t = 0; t < KCH; t++) {
        if (t < KCH - 1) CP_WAIT(1); else CP_WAIT(0);
        __syncthreads();

        if (t + 2 < KCH) prefetch(t + 2);

        const int slot = t % STAGES;
        const uint32_t aS = aBase + slot * STG_B + aOff;
        const uint32_t bS = bBase + slot * STG_B + bOff;

        #pragma unroll
        for (int kk = 0; kk < 2; kk++) {           // two k16 per chunk
            const uint32_t kb = kk * 32;           // 16 bf16 = 32B
            uint32_t a[2][4];
            LDSM_X4(a[0], aS + kb);
            LDSM_X4(a[1], aS + 16 * ROWB + kb);
            uint32_t b[4][4];
            #pragma unroll
            for (int q = 0; q < 4; q++)
                LDSM_X4(b[q], bS + q * 16 * ROWB + kb);   // non-trans (fixed)

            #pragma unroll
            for (int mt = 0; mt < 2; mt++)
                #pragma unroll
                for (int q = 0; q < 4; q++) {
                    mma16816(acc[mt][2 * q + 0], a[mt], b[q][0], b[q][1]);
                    mma16816(acc[mt][2 * q + 1], a[mt], b[q][2], b[q][3]);
                }
        }
    }

    // -------- epilogue (accumulators in registers)
    const int rBase = mStart + wm * 32 + (lane >> 2);
    const int cBase = nStart + wn * 64 + (lane & 3) * 2;

    float2 bias2[8];
    if (FUSED) {
        #pragma unroll
        for (int nt = 0; nt < 8; nt++)
            bias2[nt] = *(const float2*)(bias + cBase + nt * 8);
    }

    #pragma unroll
    for (int mt = 0; mt < 2; mt++) {
        #pragma unroll
        for (int rs = 0; rs < 2; rs++) {
            const int row = rBase + mt * 16 + rs * 8;
            float* op = out + (size_t)row * 1024;

            if (FUSED) {
                const int sv = smap[row];
                const int bb = row >> 12;                  // Lw = 4096
                const float* yrow = y2
                    + (size_t)(bb * Ssent + (sv < 0 ? 0 : sv)) * 1024;
                #pragma unroll
                for (int nt = 0; nt < 8; nt++) {
                    const int col = cBase + nt * 8;
                    float2 yv = make_float2(0.f, 0.f);
                    if (sv >= 0) yv = *(const float2*)(yrow + col);
                    float2 o;
                    o.x = fmaxf(acc[mt][nt][rs * 2 + 0] + bias2[nt].x + yv.x, 0.f);
                    o.y = fmaxf(acc[mt][nt][rs * 2 + 1] + bias2[nt].y + yv.y, 0.f);
                    *(float2*)(op + col) = o;
                }
            } else {
                #pragma unroll
                for (int nt = 0; nt < 8; nt++) {
                    const int col = cBase + nt * 8;
                    float2 o = make_float2(acc[mt][nt][rs * 2 + 0],
                                           acc[mt][nt][rs * 2 + 1]);
                    *(float2*)(op + col) = o;
                }
            }
        }
    }
}

// ---------------------------------------------------------------- launch
extern "C" void kernel_launch(void* const* d_in, const int* in_sizes, int n_in,
                              void* d_out, int out_size)
{
    const float* words = (const float*)d_in[0];  // [8, 4096, 1024]
    const float* sents = (const float*)d_in[1];  // [8, 255, 1024]
    const float* W1w   = (const float*)d_in[2];  // [1024, 2048]
    const float* W1b   = (const float*)d_in[3];  // [1024]
    const int*   smap  = (const int*)d_in[4];    // [8, 4096]
    float*       out   = (float*)d_out;          // [8, 4096, 1024]

    void *pAw, *pWa, *pWb, *pSp, *pY2;
    cudaGetSymbolAddress(&pAw, g_Aw);
    cudaGetSymbolAddress(&pWa, g_Wa);
    cudaGetSymbolAddress(&pWb, g_Wb);
    cudaGetSymbolAddress(&pSp, g_Sp);
    cudaGetSymbolAddress(&pY2, g_Y2);

    cudaFuncSetAttribute(gemm_bf16x3<true>,
                         cudaFuncAttributeMaxDynamicSharedMemorySize, SMEM_SZ);
    cudaFuncSetAttribute(gemm_bf16x3<false>,
                         cudaFuncAttributeMaxDynamicSharedMemorySize, SMEM_SZ);

    // 1) fp32 -> bf16 hi/lo splits
    split_kernel<<<Bsz * Lw, 256>>>(words, Dm, 0,    (__nv_bfloat16*)pAw);
    split_kernel<<<Dm,       256>>>(W1w,   LDW, 0,   (__nv_bfloat16*)pWa);
    split_kernel<<<Dm,       256>>>(W1w,   LDW, Dm,  (__nv_bfloat16*)pWb);
    split_kernel<<<Bsz * Ssent, 256>>>(sents, Dm, 0, (__nv_bfloat16*)pSp);

    // 2) sentence pre-projection: Y2[2048(pad), 1024]
    dim3 gridS(Dm / BN, 2048 / BM);              // 8 x 16
    gemm_bf16x3<false><<<gridS, 256, SMEM_SZ>>>(
        (const __nv_bfloat16*)pSp, (const __nv_bfloat16*)pWb,
        nullptr, nullptr, nullptr, (float*)pY2);

    // 3) main GEMM with fused gather + bias + ReLU
    dim3 gridM(Dm / BN, (Bsz * Lw) / BM);        // 8 x 256
    gemm_bf16x3<true><<<gridM, 256, SMEM_SZ>>>(
        (const __nv_bfloat16*)pAw, (const __nv_bfloat16*)pWa,
        W1b, smap, (const float*)pY2, out);
}

// round 8
// speedup vs baseline: 3.0402x; 1.6124x over previous
#include <cuda_runtime.h>
#include <cuda_fp16.h>
#include <cstdint>

// ---------------------------------------------------------------- constants
#define Dm     1024
#define Bsz    8
#define Lw     4096
#define Ssent  255

#define BM     128
#define BN     128
#define SUPER  32            // k super-chunks of width 32 (each: hi+lo parts)
#define STAGES 3
#define ROWB   80            // smem row stride bytes (32 fp16 + 16B pad)
#define TILE   (128 * ROWB)  // 10240 per tile
#define STG3   (3 * TILE)    // A_hi | A_lo | B per stage
#define SMEM_SZ (STAGES * STG3)   // 92160

// ---------------------------------------------------------------- scratch
__device__ __half g_Aw[32768ull * 2048];  // words  [hi | lo] fp16
__device__ __half g_Wa[1024ull  * 1024];  // W[:, :1024]  hi only
__device__ __half g_Wb[1024ull  * 1024];  // W[:, 1024:]  hi only
__device__ __half g_Sp[2048ull  * 2048];  // sents [hi | lo], rows>=2040 zero
__device__ float  g_Y2[2048ull  * 1024];  // sentence pre-projection

// ---------------------------------------------------------------- PTX utils
__device__ __forceinline__ uint32_t smem_u32(const void* p) {
    uint32_t a;
    asm("{ .reg .u64 t; cvta.to.shared.u64 t, %1; cvt.u32.u64 %0, t; }"
        : "=r"(a) : "l"(p));
    return a;
}
__device__ __forceinline__ void cp16(uint32_t dst, const void* src) {
    asm volatile("cp.async.cg.shared.global [%0], [%1], 16;"
                 :: "r"(dst), "l"(src));
}
#define CP_COMMIT() asm volatile("cp.async.commit_group;" ::: "memory")
#define CP_WAIT(n)  asm volatile("cp.async.wait_group %0;" :: "n"(n) : "memory")

// non-trans ldmatrix: rows hold contiguous k (A rows = m, B rows = n)
#define LDSM_X4(r, addr) \
    asm volatile("ldmatrix.sync.aligned.m8n8.x4.shared.b16 {%0,%1,%2,%3}, [%4];" \
        : "=r"((r)[0]), "=r"((r)[1]), "=r"((r)[2]), "=r"((r)[3]) : "r"(addr))

__device__ __forceinline__ void mma16816(float* c, const uint32_t* a,
                                         uint32_t b0, uint32_t b1) {
    asm volatile(
        "mma.sync.aligned.m16n8k16.row.col.f32.f16.f16.f32 "
        "{%0,%1,%2,%3}, {%4,%5,%6,%7}, {%8,%9}, {%0,%1,%2,%3};"
        : "+f"(c[0]), "+f"(c[1]), "+f"(c[2]), "+f"(c[3])
        : "r"(a[0]), "r"(a[1]), "r"(a[2]), "r"(a[3]), "r"(b0), "r"(b1));
}

// ---------------------------------------------------------------- split kernels
// fp32 row (pitch 1024) -> fp16 hi (cols 0:1024) + lo (cols 1024:2048)
__global__ __launch_bounds__(256)
void split2_f16(const float* __restrict__ src, __half* __restrict__ dst)
{
    const int r = blockIdx.x;
    const int c = threadIdx.x * 4;
    float4 v = *(const float4*)(src + (size_t)r * 1024 + c);

    __half h0 = __float2half(v.x), h1 = __float2half(v.y);
    __half h2 = __float2half(v.z), h3 = __float2half(v.w);
    __half l0 = __float2half(v.x - __half2float(h0));
    __half l1 = __float2half(v.y - __half2float(h1));
    __half l2 = __float2half(v.z - __half2float(h2));
    __half l3 = __float2half(v.w - __half2float(h3));

    __half2 hp0{h0, h1}, hp1{h2, h3}, lp0{l0, l1}, lp1{l2, l3};
    uint2 hw, lw;
    hw.x = *(uint32_t*)&hp0; hw.y = *(uint32_t*)&hp1;
    lw.x = *(uint32_t*)&lp0; lw.y = *(uint32_t*)&lp1;
    *(uint2*)(dst + (size_t)r * 2048 + c)        = hw;
    *(uint2*)(dst + (size_t)r * 2048 + 1024 + c) = lw;
}

// W row (pitch 2048 fp32) -> Wa[r,:] = fp16(W[r,0:1024]), Wb[r,:] = fp16(W[r,1024:2048])
__global__ __launch_bounds__(256)
void cvtW_f16(const float* __restrict__ W,
              __half* __restrict__ wa, __half* __restrict__ wb)
{
    const int r = blockIdx.x;
    const int c = threadIdx.x * 4;
    float4 va = *(const float4*)(W + (size_t)r * 2048 + c);
    float4 vb = *(const float4*)(W + (size_t)r * 2048 + 1024 + c);
    __half2 a0{__float2half(va.x), __float2half(va.y)};
    __half2 a1{__float2half(va.z), __float2half(va.w)};
    __half2 b0{__float2half(vb.x), __float2half(vb.y)};
    __half2 b1{__float2half(vb.z), __float2half(vb.w)};
    uint2 aw, bw;
    aw.x = *(uint32_t*)&a0; aw.y = *(uint32_t*)&a1;
    bw.x = *(uint32_t*)&b0; bw.y = *(uint32_t*)&b1;
    *(uint2*)(wa + (size_t)r * 1024 + c) = aw;
    *(uint2*)(wb + (size_t)r * 1024 + c) = bw;
}

// ---------------------------------------------------------------- GEMM kernel
// out[m,n] = A_hi[m,:].B[n,:] + A_lo[m,:].B[n,:]   (fp16 in, fp32 acc)
// FUSED: + bias + gather(Y2 via smap) + ReLU
template<bool FUSED>
__global__ __launch_bounds__(256, 2)
void gemm_f16x2(const __half* __restrict__ Ap,    // pitch 2048 [hi|lo]
                const __half* __restrict__ Bp,    // pitch 1024 [hi]
                const float* __restrict__ bias,
                const int*   __restrict__ smap,
                const float* __restrict__ y2,
                float* __restrict__ out)
{
    extern __shared__ char smem_raw[];
    const uint32_t base = smem_u32(smem_raw);

    const int tid  = threadIdx.x;
    const int lane = tid & 31;
    const int wid  = tid >> 5;
    const int wm   = wid >> 1;             // 0..3 -> M offset wm*32
    const int wn   = wid & 1;              // 0..1 -> N offset wn*64
    const int nStart = blockIdx.x * BN;    // N fastest: A block shared via L2
    const int mStart = blockIdx.y * BM;

    // prefetch super-chunk u: A_hi, A_lo, B (each 128 x 32 fp16) into slot u%3
    auto prefetch = [&](int u) {
        const uint32_t st = base + (u % STAGES) * STG3;
        const int k0 = u * 32;
        #pragma unroll
        for (int i = 0; i < 2; i++) {
            const int idx = tid + i * 256;
            const int row = idx >> 2, ch = idx & 3;
            const uint32_t so = row * ROWB + ch * 16;
            const __half* ar = Ap + (size_t)(mStart + row) * 2048 + k0 + ch * 8;
            cp16(st + so,            ar);           // A_hi
            cp16(st + TILE + so,     ar + 1024);    // A_lo
            cp16(st + 2 * TILE + so,
                 Bp + (size_t)(nStart + row) * 1024 + k0 + ch * 8);  // B
        }
        CP_COMMIT();
    };

    prefetch(0);
    prefetch(1);

    float acc[2][8][4];
    #pragma unroll
    for (int mt = 0; mt < 2; mt++)
        #pragma unroll
        for (int nt = 0; nt < 8; nt++)
            #pragma unroll
            for (int j = 0; j < 4; j++) acc[mt][nt][j] = 0.f;

    // ldmatrix lane offsets
    // A x4: lanes 0-7 m0-7|k0 , 8-15 m8-15|k0 , 16-23 m0-7|k8 , 24-31 m8-15|k8
    const uint32_t aOff = (uint32_t)(wm * 32 + (lane & 15)) * ROWB
                        + ((lane >> 4) * 16);
    // B x4: lanes 0-7 n0-7|k0 , 8-15 n0-7|k8 , 16-23 n8-15|k0 , 24-31 n8-15|k8
    const uint32_t bOff = (uint32_t)(wn * 64 + ((lane >> 4) & 1) * 8 + (lane & 7)) * ROWB
                        + (((lane >> 3) & 1) * 16);

    for (int t = 0; t < SUPER; t++) {
        if (t < SUPER - 1) CP_WAIT(1); else CP_WAIT(0);
        __syncthreads();

        if (t + 2 < SUPER) prefetch(t + 2);

        const uint32_t st  = base + (t % STAGES) * STG3;
        const uint32_t aHi = st + aOff;
        const uint32_t aLo = st + TILE + aOff;
        const uint32_t bS  = st + 2 * TILE + bOff;

        #pragma unroll
        for (int kk = 0; kk < 2; kk++) {            // two k16 per super-chunk
            const uint32_t kb = kk * 32;            // 16 fp16 = 32B
            uint32_t b[4][4];
            #pragma unroll
            for (int q = 0; q < 4; q++)
                LDSM_X4(b[q], bS + q * 16 * ROWB + kb);

            uint32_t a[2][4];
            LDSM_X4(a[0], aHi + kb);                // hi part
            LDSM_X4(a[1], aHi + 16 * ROWB + kb);
            #pragma unroll
            for (int mt = 0; mt < 2; mt++)
                #pragma unroll
                for (int q = 0; q < 4; q++) {
                    mma16816(acc[mt][2 * q + 0], a[mt], b[q][0], b[q][1]);
                    mma16816(acc[mt][2 * q + 1], a[mt], b[q][2], b[q][3]);
                }

            LDSM_X4(a[0], aLo + kb);                // lo part (same B frags)
            LDSM_X4(a[1], aLo + 16 * ROWB + kb);
            #pragma unroll
            for (int mt = 0; mt < 2; mt++)
                #pragma unroll
                for (int q = 0; q < 4; q++) {
                    mma16816(acc[mt][2 * q + 0], a[mt], b[q][0], b[q][1]);
                    mma16816(acc[mt][2 * q + 1], a[mt], b[q][2], b[q][3]);
                }
        }
    }

    // -------- epilogue (register accumulators)
    const int rBase = mStart + wm * 32 + (lane >> 2);
    const int cBase = nStart + wn * 64 + (lane & 3) * 2;

    float2 bias2[8];
    if (FUSED) {
        #pragma unroll
        for (int nt = 0; nt < 8; nt++)
            bias2[nt] = *(const float2*)(bias + cBase + nt * 8);
    }

    #pragma unroll
    for (int mt = 0; mt < 2; mt++) {
        #pragma unroll
        for (int rs = 0; rs < 2; rs++) {
            const int row = rBase + mt * 16 + rs * 8;
            float* op = out + (size_t)row * 1024;

            if (FUSED) {
                const int sv = smap[row];
                const int bb = row >> 12;                  // Lw = 4096
                const float* yrow = y2
                    + (size_t)(bb * Ssent + (sv < 0 ? 0 : sv)) * 1024;
                #pragma unroll
                for (int nt = 0; nt < 8; nt++) {
                    const int col = cBase + nt * 8;
                    float2 yv = make_float2(0.f, 0.f);
                    if (sv >= 0) yv = *(const float2*)(yrow + col);
                    float2 o;
                    o.x = fmaxf(acc[mt][nt][rs * 2 + 0] + bias2[nt].x + yv.x, 0.f);
                    o.y = fmaxf(acc[mt][nt][rs * 2 + 1] + bias2[nt].y + yv.y, 0.f);
                    *(float2*)(op + col) = o;
                }
            } else {
                #pragma unroll
                for (int nt = 0; nt < 8; nt++) {
                    const int col = cBase + nt * 8;
                    *(float2*)(op + col) =
                        make_float2(acc[mt][nt][rs * 2 + 0],
                                    acc[mt][nt][rs * 2 + 1]);
                }
            }
        }
    }
}

// ---------------------------------------------------------------- launch
extern "C" void kernel_launch(void* const* d_in, const int* in_sizes, int n_in,
                              void* d_out, int out_size)
{
    const float* words = (const float*)d_in[0];  // [8, 4096, 1024]
    const float* sents = (const float*)d_in[1];  // [8, 255, 1024]
    const float* W1w   = (const float*)d_in[2];  // [1024, 2048]
    const float* W1b   = (const float*)d_in[3];  // [1024]
    const int*   smap  = (const int*)d_in[4];    // [8, 4096]
    float*       out   = (float*)d_out;          // [8, 4096, 1024]

    void *pAw, *pWa, *pWb, *pSp, *pY2;
    cudaGetSymbolAddress(&pAw, g_Aw);
    cudaGetSymbolAddress(&pWa, g_Wa);
    cudaGetSymbolAddress(&pWb, g_Wb);
    cudaGetSymbolAddress(&pSp, g_Sp);
    cudaGetSymbolAddress(&pY2, g_Y2);

    cudaFuncSetAttribute(gemm_f16x2<true>,
                         cudaFuncAttributeMaxDynamicSharedMemorySize, SMEM_SZ);
    cudaFuncSetAttribute(gemm_f16x2<false>,
                         cudaFuncAttributeMaxDynamicSharedMemorySize, SMEM_SZ);

    // 1) conversions
    split2_f16<<<Bsz * Lw, 256>>>(words, (__half*)pAw);
    split2_f16<<<Bsz * Ssent, 256>>>(sents, (__half*)pSp);   // rows 2040+ stay 0
    cvtW_f16<<<Dm, 256>>>(W1w, (__half*)pWa, (__half*)pWb);

    // 2) sentence pre-projection: Y2[2048(pad), 1024]
    dim3 gridS(Dm / BN, 2048 / BM);              // 8 x 16
    gemm_f16x2<false><<<gridS, 256, SMEM_SZ>>>(
        (const __half*)pSp, (const __half*)pWb,
        nullptr, nullptr, nullptr, (float*)pY2);

    // 3) main GEMM with fused gather + bias + ReLU
    dim3 gridM(Dm / BN, (Bsz * Lw) / BM);        // 8 x 256
    gemm_f16x2<true><<<gridM, 256, SMEM_SZ>>>(
        (const __half*)pAw, (const __half*)pWa,
        W1b, smap, (const float*)pY2, out);
}

// round 9
// speedup vs baseline: 4.6520x; 1.5302x over previous
#include <cuda_runtime.h>
#include <cuda_fp16.h>
#include <cstdint>

// ---------------------------------------------------------------- constants
#define Dm     1024
#define Bsz    8
#define Lw     4096
#define Ssent  255

#define BM     128
#define BN     128
#define NCHUNK 32            // k chunks of width 32
#define STAGES 3
#define ROWB   80            // smem row stride bytes (32 fp16 + 16B pad)
#define TILE   (128 * ROWB)  // 10240 per tile
#define STG2   (2 * TILE)    // A | B per stage
#define SMEM_SZ (STAGES * STG2)   // 61440 -> 2 CTAs/SM

// ---------------------------------------------------------------- scratch
__device__ __half g_Aw[32768ull * 1024];  // words fp16
__device__ __half g_Wa[1024ull  * 1024];  // W[:, :1024]
__device__ __half g_Wb[1024ull  * 1024];  // W[:, 1024:]
__device__ __half g_Sp[2048ull  * 1024];  // sents fp16, rows>=2040 zero
__device__ float  g_Y2[2048ull  * 1024];  // sentence pre-projection

// ---------------------------------------------------------------- PTX utils
__device__ __forceinline__ uint32_t smem_u32(const void* p) {
    uint32_t a;
    asm("{ .reg .u64 t; cvta.to.shared.u64 t, %1; cvt.u32.u64 %0, t; }"
        : "=r"(a) : "l"(p));
    return a;
}
__device__ __forceinline__ void cp16(uint32_t dst, const void* src) {
    asm volatile("cp.async.cg.shared.global [%0], [%1], 16;"
                 :: "r"(dst), "l"(src));
}
#define CP_COMMIT() asm volatile("cp.async.commit_group;" ::: "memory")
#define CP_WAIT(n)  asm volatile("cp.async.wait_group %0;" :: "n"(n) : "memory")

// non-trans ldmatrix: rows hold contiguous k (A rows = m, B rows = n)
#define LDSM_X4(r, addr) \
    asm volatile("ldmatrix.sync.aligned.m8n8.x4.shared.b16 {%0,%1,%2,%3}, [%4];" \
        : "=r"((r)[0]), "=r"((r)[1]), "=r"((r)[2]), "=r"((r)[3]) : "r"(addr))

__device__ __forceinline__ void mma16816(float* c, const uint32_t* a,
                                         uint32_t b0, uint32_t b1) {
    asm volatile(
        "mma.sync.aligned.m16n8k16.row.col.f32.f16.f16.f32 "
        "{%0,%1,%2,%3}, {%4,%5,%6,%7}, {%8,%9}, {%0,%1,%2,%3};"
        : "+f"(c[0]), "+f"(c[1]), "+f"(c[2]), "+f"(c[3])
        : "r"(a[0]), "r"(a[1]), "r"(a[2]), "r"(a[3]), "r"(b0), "r"(b1));
}

// ---------------------------------------------------------------- conversions
// fp32 row (pitch 1024) -> fp16 row (pitch 1024)
__global__ __launch_bounds__(256)
void cvt_f16(const float* __restrict__ src, __half* __restrict__ dst)
{
    const int r = blockIdx.x;
    const int c = threadIdx.x * 4;
    float4 v = *(const float4*)(src + (size_t)r * 1024 + c);
    __half2 p0{__float2half(v.x), __float2half(v.y)};
    __half2 p1{__float2half(v.z), __float2half(v.w)};
    uint2 w;
    w.x = *(uint32_t*)&p0; w.y = *(uint32_t*)&p1;
    *(uint2*)(dst + (size_t)r * 1024 + c) = w;
}

// W row (pitch 2048) -> Wa[r,:] = fp16(W[r,0:1024]), Wb[r,:] = fp16(W[r,1024:2048])
__global__ __launch_bounds__(256)
void cvtW_f16(const float* __restrict__ W,
              __half* __restrict__ wa, __half* __restrict__ wb)
{
    const int r = blockIdx.x;
    const int c = threadIdx.x * 4;
    float4 va = *(const float4*)(W + (size_t)r * 2048 + c);
    float4 vb = *(const float4*)(W + (size_t)r * 2048 + 1024 + c);
    __half2 a0{__float2half(va.x), __float2half(va.y)};
    __half2 a1{__float2half(va.z), __float2half(va.w)};
    __half2 b0{__float2half(vb.x), __float2half(vb.y)};
    __half2 b1{__float2half(vb.z), __float2half(vb.w)};
    uint2 aw, bw;
    aw.x = *(uint32_t*)&a0; aw.y = *(uint32_t*)&a1;
    bw.x = *(uint32_t*)&b0; bw.y = *(uint32_t*)&b1;
    *(uint2*)(wa + (size_t)r * 1024 + c) = aw;
    *(uint2*)(wb + (size_t)r * 1024 + c) = bw;
}

// ---------------------------------------------------------------- GEMM kernel
// out[m,n] = A[m,:].B[n,:]  (fp16 in, fp32 acc), K = 1024
// FUSED: + bias + gather(Y2 via smap) + ReLU
template<bool FUSED>
__global__ __launch_bounds__(256, 2)
void gemm_f16(const __half* __restrict__ Ap,    // pitch 1024
              const __half* __restrict__ Bp,    // pitch 1024
              const float* __restrict__ bias,
              const int*   __restrict__ smap,
              const float* __restrict__ y2,
              float* __restrict__ out)
{
    extern __shared__ char smem_raw[];
    const uint32_t base = smem_u32(smem_raw);

    const int tid  = threadIdx.x;
    const int lane = tid & 31;
    const int wid  = tid >> 5;
    const int wm   = wid >> 1;             // 0..3 -> M offset wm*32
    const int wn   = wid & 1;              // 0..1 -> N offset wn*64
    const int nStart = blockIdx.x * BN;    // N fastest: A block shared via L2
    const int mStart = blockIdx.y * BM;

    // prefetch chunk u: A and B (each 128 x 32 fp16) into slot u%3
    auto prefetch = [&](int u) {
        const uint32_t st = base + (u % STAGES) * STG2;
        const int k0 = u * 32;
        #pragma unroll
        for (int i = 0; i < 2; i++) {
            const int idx = tid + i * 256;
            const int row = idx >> 2, ch = idx & 3;
            const uint32_t so = row * ROWB + ch * 16;
            cp16(st + so,
                 Ap + (size_t)(mStart + row) * 1024 + k0 + ch * 8);
            cp16(st + TILE + so,
                 Bp + (size_t)(nStart + row) * 1024 + k0 + ch * 8);
        }
        CP_COMMIT();
    };

    prefetch(0);
    prefetch(1);

    float acc[2][8][4];
    #pragma unroll
    for (int mt = 0; mt < 2; mt++)
        #pragma unroll
        for (int nt = 0; nt < 8; nt++)
            #pragma unroll
            for (int j = 0; j < 4; j++) acc[mt][nt][j] = 0.f;

    // ldmatrix lane offsets
    // A x4: lanes 0-7 m0-7|k0 , 8-15 m8-15|k0 , 16-23 m0-7|k8 , 24-31 m8-15|k8
    const uint32_t aOff = (uint32_t)(wm * 32 + (lane & 15)) * ROWB
                        + ((lane >> 4) * 16);
    // B x4: lanes 0-7 n0-7|k0 , 8-15 n0-7|k8 , 16-23 n8-15|k0 , 24-31 n8-15|k8
    const uint32_t bOff = (uint32_t)(wn * 64 + ((lane >> 4) & 1) * 8 + (lane & 7)) * ROWB
                        + (((lane >> 3) & 1) * 16);

    for (int t = 0; t < NCHUNK; t++) {
        if (t < NCHUNK - 1) CP_WAIT(1); else CP_WAIT(0);
        __syncthreads();

        if (t + 2 < NCHUNK) prefetch(t + 2);

        const uint32_t st = base + (t % STAGES) * STG2;
        const uint32_t aS = st + aOff;
        const uint32_t bS = st + TILE + bOff;

        #pragma unroll
        for (int kk = 0; kk < 2; kk++) {            // two k16 per chunk
            const uint32_t kb = kk * 32;            // 16 fp16 = 32B
            uint32_t b[4][4];
            #pragma unroll
            for (int q = 0; q < 4; q++)
                LDSM_X4(b[q], bS + q * 16 * ROWB + kb);

            uint32_t a[2][4];
            LDSM_X4(a[0], aS + kb);
            LDSM_X4(a[1], aS + 16 * ROWB + kb);

            #pragma unroll
            for (int mt = 0; mt < 2; mt++)
                #pragma unroll
                for (int q = 0; q < 4; q++) {
                    mma16816(acc[mt][2 * q + 0], a[mt], b[q][0], b[q][1]);
                    mma16816(acc[mt][2 * q + 1], a[mt], b[q][2], b[q][3]);
                }
        }
    }

    // -------- epilogue (register accumulators)
    const int rBase = mStart + wm * 32 + (lane >> 2);
    const int cBase = nStart + wn * 64 + (lane & 3) * 2;

    float2 bias2[8];
    if (FUSED) {
        #pragma unroll
        for (int nt = 0; nt < 8; nt++)
            bias2[nt] = *(const float2*)(bias + cBase + nt * 8);
    }

    #pragma unroll
    for (int mt = 0; mt < 2; mt++) {
        #pragma unroll
        for (int rs = 0; rs < 2; rs++) {
            const int row = rBase + mt * 16 + rs * 8;
            float* op = out + (size_t)row * 1024;

            if (FUSED) {
                const int sv = smap[row];
                const int bb = row >> 12;                  // Lw = 4096
                const float* yrow = y2
                    + (size_t)(bb * Ssent + (sv < 0 ? 0 : sv)) * 1024;
                #pragma unroll
                for (int nt = 0; nt < 8; nt++) {
                    const int col = cBase + nt * 8;
                    float2 yv = make_float2(0.f, 0.f);
                    if (sv >= 0) yv = *(const float2*)(yrow + col);
                    float2 o;
                    o.x = fmaxf(acc[mt][nt][rs * 2 + 0] + bias2[nt].x + yv.x, 0.f);
                    o.y = fmaxf(acc[mt][nt][rs * 2 + 1] + bias2[nt].y + yv.y, 0.f);
                    *(float2*)(op + col) = o;
                }
            } else {
                #pragma unroll
                for (int nt = 0; nt < 8; nt++) {
                    const int col = cBase + nt * 8;
                    *(float2*)(op + col) =
                        make_float2(acc[mt][nt][rs * 2 + 0],
                                    acc[mt][nt][rs * 2 + 1]);
                }
            }
        }
    }
}

// ---------------------------------------------------------------- launch
extern "C" void kernel_launch(void* const* d_in, const int* in_sizes, int n_in,
                              void* d_out, int out_size)
{
    const float* words = (const float*)d_in[0];  // [8, 4096, 1024]
    const float* sents = (const float*)d_in[1];  // [8, 255, 1024]
    const float* W1w   = (const float*)d_in[2];  // [1024, 2048]
    const float* W1b   = (const float*)d_in[3];  // [1024]
    const int*   smap  = (const int*)d_in[4];    // [8, 4096]
    float*       out   = (float*)d_out;          // [8, 4096, 1024]

    void *pAw, *pWa, *pWb, *pSp, *pY2;
    cudaGetSymbolAddress(&pAw, g_Aw);
    cudaGetSymbolAddress(&pWa, g_Wa);
    cudaGetSymbolAddress(&pWb, g_Wb);
    cudaGetSymbolAddress(&pSp, g_Sp);
    cudaGetSymbolAddress(&pY2, g_Y2);

    cudaFuncSetAttribute(gemm_f16<true>,
                         cudaFuncAttributeMaxDynamicSharedMemorySize, SMEM_SZ);
    cudaFuncSetAttribute(gemm_f16<false>,
                         cudaFuncAttributeMaxDynamicSharedMemorySize, SMEM_SZ);

    // 1) conversions
    cvt_f16<<<Bsz * Lw, 256>>>(words, (__half*)pAw);
    cvt_f16<<<Bsz * Ssent, 256>>>(sents, (__half*)pSp);   // rows 2040+ stay 0
    cvtW_f16<<<Dm, 256>>>(W1w, (__half*)pWa, (__half*)pWb);

    // 2) sentence pre-projection: Y2[2048(pad), 1024]
    dim3 gridS(Dm / BN, 2048 / BM);              // 8 x 16
    gemm_f16<false><<<gridS, 256, SMEM_SZ>>>(
        (const __half*)pSp, (const __half*)pWb,
        nullptr, nullptr, nullptr, (float*)pY2);

    // 3) main GEMM with fused gather + bias + ReLU
    dim3 gridM(Dm / BN, (Bsz * Lw) / BM);        // 8 x 256
    gemm_f16<true><<<gridM, 256, SMEM_SZ>>>(
        (const __half*)pAw, (const __half*)pWa,
        W1b, smap, (const float*)pY2, out);
}

// round 11
// speedup vs baseline: 4.7778x; 1.0270x over previous
#include <cuda_runtime.h>
#include <cuda_fp16.h>
#include <cstdint>

// ---------------------------------------------------------------- constants
#define Dm     1024
#define Bsz    8
#define Lw     4096
#define Ssent  255

#define NCHUNK 32            // k chunks of width 32
#define STAGES 3
#define ROWB   80            // smem row stride bytes (32 fp16 + 16B pad)
#define TILE_A (128 * ROWB)  // A tile bytes per stage (BM = 128 always)

// ---------------------------------------------------------------- scratch
__device__ __half g_Aw[32768ull * 1024];  // words fp16
__device__ __half g_Wa[1024ull  * 1024];  // W[:, :1024]
__device__ __half g_Wb[1024ull  * 1024];  // W[:, 1024:]
__device__ __half g_Sp[2048ull  * 1024];  // sents fp16, rows>=2040 zero
__device__ float  g_Y2[2048ull  * 1024];  // sentence pre-projection

// ---------------------------------------------------------------- PTX utils
__device__ __forceinline__ uint32_t smem_u32(const void* p) {
    uint32_t a;
    asm("{ .reg .u64 t; cvta.to.shared.u64 t, %1; cvt.u32.u64 %0, t; }"
        : "=r"(a) : "l"(p));
    return a;
}
__device__ __forceinline__ void cp16(uint32_t dst, const void* src) {
    asm volatile("cp.async.cg.shared.global [%0], [%1], 16;"
                 :: "r"(dst), "l"(src));
}
#define CP_COMMIT() asm volatile("cp.async.commit_group;" ::: "memory")
#define CP_WAIT(n)  asm volatile("cp.async.wait_group %0;" :: "n"(n) : "memory")

// non-trans ldmatrix: rows hold contiguous k (A rows = m, B rows = n)
#define LDSM_X4(r, addr) \
    asm volatile("ldmatrix.sync.aligned.m8n8.x4.shared.b16 {%0,%1,%2,%3}, [%4];" \
        : "=r"((r)[0]), "=r"((r)[1]), "=r"((r)[2]), "=r"((r)[3]) : "r"(addr))

__device__ __forceinline__ void mma16816(float* c, const uint32_t* a,
                                         uint32_t b0, uint32_t b1) {
    asm volatile(
        "mma.sync.aligned.m16n8k16.row.col.f32.f16.f16.f32 "
        "{%0,%1,%2,%3}, {%4,%5,%6,%7}, {%8,%9}, {%0,%1,%2,%3};"
        : "+f"(c[0]), "+f"(c[1]), "+f"(c[2]), "+f"(c[3])
        : "r"(a[0]), "r"(a[1]), "r"(a[2]), "r"(a[3]), "r"(b0), "r"(b1));
}

// ---------------------------------------------------------------- conversions
// Bulk fp32 -> fp16, dense linear buffers. 4 front-batched float4 per thread
// (MLP=4 -> DRAM latency fully overlapped). grid*256*4 float4 must equal n4.
__global__ __launch_bounds__(256)
void cvt_bulk_f16(const float4* __restrict__ src, uint2* __restrict__ dst)
{
    const size_t N = (size_t)gridDim.x * 256;
    const size_t t = (size_t)blockIdx.x * 256 + threadIdx.x;

    float4 v[4];
    #pragma unroll
    for (int k = 0; k < 4; k++) v[k] = src[t + k * N];   // front-batched loads

    #pragma unroll
    for (int k = 0; k < 4; k++) {
        __half2 p0 = __float22half2_rn(make_float2(v[k].x, v[k].y));
        __half2 p1 = __float22half2_rn(make_float2(v[k].z, v[k].w));
        uint2 w;
        w.x = *(uint32_t*)&p0; w.y = *(uint32_t*)&p1;
        dst[t + k * N] = w;
    }
}

// W row (pitch 2048) -> Wa[r,:] = fp16(W[r,0:1024]), Wb[r,:] = fp16(W[r,1024:2048])
__global__ __launch_bounds__(256)
void cvtW_f16(const float* __restrict__ W,
              __half* __restrict__ wa, __half* __restrict__ wb)
{
    const int r = blockIdx.x;
    const int c = threadIdx.x * 4;
    float4 va = *(const float4*)(W + (size_t)r * 2048 + c);
    float4 vb = *(const float4*)(W + (size_t)r * 2048 + 1024 + c);
    __half2 a0 = __float22half2_rn(make_float2(va.x, va.y));
    __half2 a1 = __float22half2_rn(make_float2(va.z, va.w));
    __half2 b0 = __float22half2_rn(make_float2(vb.x, vb.y));
    __half2 b1 = __float22half2_rn(make_float2(vb.z, vb.w));
    uint2 aw, bw;
    aw.x = *(uint32_t*)&a0; aw.y = *(uint32_t*)&a1;
    bw.x = *(uint32_t*)&b0; bw.y = *(uint32_t*)&b1;
    *(uint2*)(wa + (size_t)r * 1024 + c) = aw;
    *(uint2*)(wb + (size_t)r * 1024 + c) = bw;
}

// ---------------------------------------------------------------- GEMM kernel
// out[m,n] = A[m,:].B[n,:]  (fp16 in, fp32 acc), K = 1024, BM = 128.
// QN: n8-subtile pairs per warp; BN = QN*32 (QN=4 -> BN=128, QN=2 -> BN=64).
// FUSED: + bias + gather(Y2 via smap) + ReLU
template<bool FUSED, int QN>
__global__ __launch_bounds__(256, 2)
void gemm_f16(const __half* __restrict__ Ap,    // pitch 1024
              const __half* __restrict__ Bp,    // pitch 1024
              const float* __restrict__ bias,
              const int*   __restrict__ smap,
              const float* __restrict__ y2,
              float* __restrict__ out)
{
    constexpr int BN     = QN * 32;
    constexpr int TILE_B = BN * ROWB;
    constexpr int STG    = TILE_A + TILE_B;

    extern __shared__ char smem_raw[];
    const uint32_t base = smem_u32(smem_raw);

    const int tid  = threadIdx.x;
    const int lane = tid & 31;
    const int wid  = tid >> 5;
    const int wm   = wid >> 1;             // 0..3 -> M offset wm*32
    const int wn   = wid & 1;              // 0..1 -> N offset wn*(BN/2)
    const int nStart = blockIdx.x * BN;    // N fastest: A block shared via L2
    const int mStart = blockIdx.y * 128;

    // prefetch chunk u: A (128x32) and B (BNx32) fp16 into slot u%3
    auto prefetch = [&](int u) {
        const uint32_t st = base + (u % STAGES) * STG;
        const int k0 = u * 32;
        #pragma unroll
        for (int i = 0; i < 2; i++) {                      // A: 512 tasks
            const int idx = tid + i * 256;
            const int row = idx >> 2, ch = idx & 3;
            cp16(st + row * ROWB + ch * 16,
                 Ap + (size_t)(mStart + row) * 1024 + k0 + ch * 8);
        }
        #pragma unroll
        for (int i = 0; i < QN / 2; i++) {                 // B: BN*4 tasks
            const int idx = tid + i * 256;
            const int row = idx >> 2, ch = idx & 3;
            cp16(st + TILE_A + row * ROWB + ch * 16,
                 Bp + (size_t)(nStart + row) * 1024 + k0 + ch * 8);
        }
        CP_COMMIT();
    };

    prefetch(0);
    prefetch(1);

    float acc[2][2 * QN][4];
    #pragma unroll
    for (int mt = 0; mt < 2; mt++)
        #pragma unroll
        for (int nt = 0; nt < 2 * QN; nt++)
            #pragma unroll
            for (int j = 0; j < 4; j++) acc[mt][nt][j] = 0.f;

    // ldmatrix lane offsets
    // A x4: lanes 0-7 m0-7|k0 , 8-15 m8-15|k0 , 16-23 m0-7|k8 , 24-31 m8-15|k8
    const uint32_t aOff = (uint32_t)(wm * 32 + (lane & 15)) * ROWB
                        + ((lane >> 4) * 16);
    // B x4: lanes 0-7 n0-7|k0 , 8-15 n0-7|k8 , 16-23 n8-15|k0 , 24-31 n8-15|k8
    const uint32_t bOff = (uint32_t)(wn * (BN / 2) + ((lane >> 4) & 1) * 8 + (lane & 7)) * ROWB
                        + (((lane >> 3) & 1) * 16);

    for (int t = 0; t < NCHUNK; t++) {
        if (t < NCHUNK - 1) CP_WAIT(1); else CP_WAIT(0);
        __syncthreads();

        if (t + 2 < NCHUNK) prefetch(t + 2);

        const uint32_t st = base + (t % STAGES) * STG;
        const uint32_t aS = st + aOff;
        const uint32_t bS = st + TILE_A + bOff;

        #pragma unroll
        for (int kk = 0; kk < 2; kk++) {            // two k16 per chunk
            const uint32_t kb = kk * 32;            // 16 fp16 = 32B
            uint32_t b[QN][4];
            #pragma unroll
            for (int q = 0; q < QN; q++)
                LDSM_X4(b[q], bS + q * 16 * ROWB + kb);

            uint32_t a[2][4];
            LDSM_X4(a[0], aS + kb);
            LDSM_X4(a[1], aS + 16 * ROWB + kb);

            #pragma unroll
            for (int mt = 0; mt < 2; mt++)
                #pragma unroll
                for (int q = 0; q < QN; q++) {
                    mma16816(acc[mt][2 * q + 0], a[mt], b[q][0], b[q][1]);
                    mma16816(acc[mt][2 * q + 1], a[mt], b[q][2], b[q][3]);
                }
        }
    }

    // -------- epilogue (register accumulators)
    const int rBase = mStart + wm * 32 + (lane >> 2);
    const int cBase = nStart + wn * (BN / 2) + (lane & 3) * 2;

    float2 bias2[2 * QN];
    if (FUSED) {
        #pragma unroll
        for (int nt = 0; nt < 2 * QN; nt++)
            bias2[nt] = *(const float2*)(bias + cBase + nt * 8);
    }

    #pragma unroll
    for (int mt = 0; mt < 2; mt++) {
        #pragma unroll
        for (int rs = 0; rs < 2; rs++) {
            const int row = rBase + mt * 16 + rs * 8;
            float* op = out + (size_t)row * 1024;

            if (FUSED) {
                const int sv = smap[row];
                const int bb = row >> 12;                  // Lw = 4096
                const float* yrow = y2
                    + (size_t)(bb * Ssent + (sv < 0 ? 0 : sv)) * 1024;
                #pragma unroll
                for (int nt = 0; nt < 2 * QN; nt++) {
                    const int col = cBase + nt * 8;
                    float2 yv = make_float2(0.f, 0.f);
                    if (sv >= 0) yv = *(const float2*)(yrow + col);
                    float2 o;
                    o.x = fmaxf(acc[mt][nt][rs * 2 + 0] + bias2[nt].x + yv.x, 0.f);
                    o.y = fmaxf(acc[mt][nt][rs * 2 + 1] + bias2[nt].y + yv.y, 0.f);
                    *(float2*)(op + col) = o;
                }
            } else {
                #pragma unroll
                for (int nt = 0; nt < 2 * QN; nt++) {
                    const int col = cBase + nt * 8;
                    *(float2*)(op + col) =
                        make_float2(acc[mt][nt][rs * 2 + 0],
                                    acc[mt][nt][rs * 2 + 1]);
                }
            }
        }
    }
}

// ---------------------------------------------------------------- launch
extern "C" void kernel_launch(void* const* d_in, const int* in_sizes, int n_in,
                              void* d_out, int out_size)
{
    const float* words = (const float*)d_in[0];  // [8, 4096, 1024]
    const float* sents = (const float*)d_in[1];  // [8, 255, 1024]
    const float* W1w   = (const float*)d_in[2];  // [1024, 2048]
    const float* W1b   = (const float*)d_in[3];  // [1024]
    const int*   smap  = (const int*)d_in[4];    // [8, 4096]
    float*       out   = (float*)d_out;          // [8, 4096, 1024]

    void *pAw, *pWa, *pWb, *pSp, *pY2;
    cudaGetSymbolAddress(&pAw, g_Aw);
    cudaGetSymbolAddress(&pWa, g_Wa);
    cudaGetSymbolAddress(&pWb, g_Wb);
    cudaGetSymbolAddress(&pSp, g_Sp);
    cudaGetSymbolAddress(&pY2, g_Y2);

    constexpr int SM_MAIN = STAGES * (TILE_A + 128 * ROWB);   // 61440
    constexpr int SM_SENT = STAGES * (TILE_A + 64 * ROWB);    // 46080
    cudaFuncSetAttribute((const void*)gemm_f16<true, 4>,
                         cudaFuncAttributeMaxDynamicSharedMemorySize, SM_MAIN);
    cudaFuncSetAttribute((const void*)gemm_f16<false, 2>,
                         cudaFuncAttributeMaxDynamicSharedMemorySize, SM_SENT);

    // 1) conversions (bulk: 4 float4 per thread, MLP=4)
    //    words: 33554432 floats = 8388608 float4 -> 8192 blocks
    cvt_bulk_f16<<<8192, 256>>>((const float4*)words, (uint2*)pAw);
    //    sents: 2088960 floats = 522240 float4 -> 510 blocks
    cvt_bulk_f16<<<510, 256>>>((const float4*)sents, (uint2*)pSp);
    cvtW_f16<<<Dm, 256>>>(W1w, (__half*)pWa, (__half*)pWb);

    // 2) sentence pre-projection: Y2[2048(pad), 1024], BN=64 -> 256 CTAs
    dim3 gridS(Dm / 64, 2048 / 128);             // 16 x 16
    gemm_f16<false, 2><<<gridS, 256, SM_SENT>>>(
        (const __half*)pSp, (const __half*)pWb,
        nullptr, nullptr, nullptr, (float*)pY2);

    // 3) main GEMM with fused gather + bias + ReLU, BN=128
    dim3 gridM(Dm / 128, (Bsz * Lw) / 128);      // 8 x 256
    gemm_f16<true, 4><<<gridM, 256, SM_MAIN>>>(
        (const __half*)pAw, (const __half*)pWa,
        W1b, smap, (const float*)pY2, out);
}

// round 14
// speedup vs baseline: 4.8003x; 1.0047x over previous
#include <cuda_runtime.h>
#include <cuda_fp16.h>
#include <cstdint>

// ---------------------------------------------------------------- constants
#define Dm     1024
#define Bsz    8
#define Lw     4096
#define Ssent  255

#define NCHUNK 32            // k chunks of width 32
#define STAGES 3
#define ROWB   80            // smem row stride bytes (32 fp16 + 16B pad)
#define TILE_A (128 * ROWB)  // A tile bytes per stage (BM = 128 always)

// ---------------------------------------------------------------- scratch
__device__ __half g_Aw[32768ull * 1024];  // words fp16
__device__ __half g_Wa[1024ull  * 1024];  // W[:, :1024]
__device__ __half g_Wb[1024ull  * 1024];  // W[:, 1024:]
__device__ __half g_Sp[2048ull  * 1024];  // sents fp16, rows>=2040 zero
__device__ float  g_Y2[2048ull  * 1024];  // sentence pre-projection

// ---------------------------------------------------------------- streams
// Created once at process start (host-side objects only; no device memory).
// kernel_launch performs the same fork-join work every call -> deterministic
// and graph-capturable (event record/wait become graph edges).
static cudaStream_t s_sb;
static cudaEvent_t  s_fork, s_join;
static struct StreamInit {
    StreamInit() {
        cudaStreamCreateWithFlags(&s_sb, cudaStreamNonBlocking);
        cudaEventCreateWithFlags(&s_fork, cudaEventDisableTiming);
        cudaEventCreateWithFlags(&s_join, cudaEventDisableTiming);
    }
} s_streamInit;

// ---------------------------------------------------------------- PTX utils
__device__ __forceinline__ uint32_t smem_u32(const void* p) {
    uint32_t a;
    asm("{ .reg .u64 t; cvta.to.shared.u64 t, %1; cvt.u32.u64 %0, t; }"
        : "=r"(a) : "l"(p));
    return a;
}
__device__ __forceinline__ void cp16(uint32_t dst, const void* src) {
    asm volatile("cp.async.cg.shared.global [%0], [%1], 16;"
                 :: "r"(dst), "l"(src));
}
#define CP_COMMIT() asm volatile("cp.async.commit_group;" ::: "memory")
#define CP_WAIT(n)  asm volatile("cp.async.wait_group %0;" :: "n"(n) : "memory")

// non-trans ldmatrix: rows hold contiguous k (A rows = m, B rows = n)
#define LDSM_X4(r, addr) \
    asm volatile("ldmatrix.sync.aligned.m8n8.x4.shared.b16 {%0,%1,%2,%3}, [%4];" \
        : "=r"((r)[0]), "=r"((r)[1]), "=r"((r)[2]), "=r"((r)[3]) : "r"(addr))

__device__ __forceinline__ void mma16816(float* c, const uint32_t* a,
                                         uint32_t b0, uint32_t b1) {
    asm volatile(
        "mma.sync.aligned.m16n8k16.row.col.f32.f16.f16.f32 "
        "{%0,%1,%2,%3}, {%4,%5,%6,%7}, {%8,%9}, {%0,%1,%2,%3};"
        : "+f"(c[0]), "+f"(c[1]), "+f"(c[2]), "+f"(c[3])
        : "r"(a[0]), "r"(a[1]), "r"(a[2]), "r"(a[3]), "r"(b0), "r"(b1));
}

// ---------------------------------------------------------------- conversions
// Bulk fp32 -> fp16, dense linear buffers. 4 front-batched float4 per thread
// (MLP=4 -> DRAM latency fully overlapped). grid*256*4 float4 must equal n4.
__global__ __launch_bounds__(256)
void cvt_bulk_f16(const float4* __restrict__ src, uint2* __restrict__ dst)
{
    const size_t N = (size_t)gridDim.x * 256;
    const size_t t = (size_t)blockIdx.x * 256 + threadIdx.x;

    float4 v[4];
    #pragma unroll
    for (int k = 0; k < 4; k++) v[k] = src[t + k * N];   // front-batched loads

    #pragma unroll
    for (int k = 0; k < 4; k++) {
        __half2 p0 = __float22half2_rn(make_float2(v[k].x, v[k].y));
        __half2 p1 = __float22half2_rn(make_float2(v[k].z, v[k].w));
        uint2 w;
        w.x = *(uint32_t*)&p0; w.y = *(uint32_t*)&p1;
        dst[t + k * N] = w;
    }
}

// W row (pitch 2048) -> Wa[r,:] = fp16(W[r,0:1024]), Wb[r,:] = fp16(W[r,1024:2048])
__global__ __launch_bounds__(256)
void cvtW_f16(const float* __restrict__ W,
              __half* __restrict__ wa, __half* __restrict__ wb)
{
    const int r = blockIdx.x;
    const int c = threadIdx.x * 4;
    float4 va = *(const float4*)(W + (size_t)r * 2048 + c);
    float4 vb = *(const float4*)(W + (size_t)r * 2048 + 1024 + c);
    __half2 a0 = __float22half2_rn(make_float2(va.x, va.y));
    __half2 a1 = __float22half2_rn(make_float2(va.z, va.w));
    __half2 b0 = __float22half2_rn(make_float2(vb.x, vb.y));
    __half2 b1 = __float22half2_rn(make_float2(vb.z, vb.w));
    uint2 aw, bw;
    aw.x = *(uint32_t*)&a0; aw.y = *(uint32_t*)&a1;
    bw.x = *(uint32_t*)&b0; bw.y = *(uint32_t*)&b1;
    *(uint2*)(wa + (size_t)r * 1024 + c) = aw;
    *(uint2*)(wb + (size_t)r * 1024 + c) = bw;
}

// ---------------------------------------------------------------- GEMM kernel
// out[m,n] = A[m,:].B[n,:]  (fp16 in, fp32 acc), K = 1024, BM = 128.
// QN: n8-subtile pairs per warp; BN = QN*32 (QN=4 -> BN=128, QN=2 -> BN=64).
// FUSED: + bias + gather(Y2 via smap) + ReLU
template<bool FUSED, int QN>
__global__ __launch_bounds__(256, 2)
void gemm_f16(const __half* __restrict__ Ap,    // pitch 1024
              const __half* __restrict__ Bp,    // pitch 1024
              const float* __restrict__ bias,
              const int*   __restrict__ smap,
              const float* __restrict__ y2,
              float* __restrict__ out)
{
    constexpr int BN     = QN * 32;
    constexpr int TILE_B = BN * ROWB;
    constexpr int STG    = TILE_A + TILE_B;

    extern __shared__ char smem_raw[];
    const uint32_t base = smem_u32(smem_raw);

    const int tid  = threadIdx.x;
    const int lane = tid & 31;
    const int wid  = tid >> 5;
    const int wm   = wid >> 1;             // 0..3 -> M offset wm*32
    const int wn   = wid & 1;              // 0..1 -> N offset wn*(BN/2)
    const int nStart = blockIdx.x * BN;    // N fastest: A block shared via L2
    const int mStart = blockIdx.y * 128;

    // prefetch chunk u: A (128x32) and B (BNx32) fp16 into slot u%3
    auto prefetch = [&](int u) {
        const uint32_t st = base + (u % STAGES) * STG;
        const int k0 = u * 32;
        #pragma unroll
        for (int i = 0; i < 2; i++) {                      // A: 512 tasks
            const int idx = tid + i * 256;
            const int row = idx >> 2, ch = idx & 3;
            cp16(st + row * ROWB + ch * 16,
                 Ap + (size_t)(mStart + row) * 1024 + k0 + ch * 8);
        }
        #pragma unroll
        for (int i = 0; i < QN / 2; i++) {                 // B: BN*4 tasks
            const int idx = tid + i * 256;
            const int row = idx >> 2, ch = idx & 3;
            cp16(st + TILE_A + row * ROWB + ch * 16,
                 Bp + (size_t)(nStart + row) * 1024 + k0 + ch * 8);
        }
        CP_COMMIT();
    };

    prefetch(0);
    prefetch(1);

    float acc[2][2 * QN][4];
    #pragma unroll
    for (int mt = 0; mt < 2; mt++)
        #pragma unroll
        for (int nt = 0; nt < 2 * QN; nt++)
            #pragma unroll
            for (int j = 0; j < 4; j++) acc[mt][nt][j] = 0.f;

    // ldmatrix lane offsets
    // A x4: lanes 0-7 m0-7|k0 , 8-15 m8-15|k0 , 16-23 m0-7|k8 , 24-31 m8-15|k8
    const uint32_t aOff = (uint32_t)(wm * 32 + (lane & 15)) * ROWB
                        + ((lane >> 4) * 16);
    // B x4: lanes 0-7 n0-7|k0 , 8-15 n0-7|k8 , 16-23 n8-15|k0 , 24-31 n8-15|k8
    const uint32_t bOff = (uint32_t)(wn * (BN / 2) + ((lane >> 4) & 1) * 8 + (lane & 7)) * ROWB
                        + (((lane >> 3) & 1) * 16);

    for (int t = 0; t < NCHUNK; t++) {
        if (t < NCHUNK - 1) CP_WAIT(1); else CP_WAIT(0);
        __syncthreads();

        if (t + 2 < NCHUNK) prefetch(t + 2);

        const uint32_t st = base + (t % STAGES) * STG;
        const uint32_t aS = st + aOff;
        const uint32_t bS = st + TILE_A + bOff;

        #pragma unroll
        for (int kk = 0; kk < 2; kk++) {            // two k16 per chunk
            const uint32_t kb = kk * 32;            // 16 fp16 = 32B
            uint32_t b[QN][4];
            #pragma unroll
            for (int q = 0; q < QN; q++)
                LDSM_X4(b[q], bS + q * 16 * ROWB + kb);

            uint32_t a[2][4];
            LDSM_X4(a[0], aS + kb);
            LDSM_X4(a[1], aS + 16 * ROWB + kb);

            #pragma unroll
            for (int mt = 0; mt < 2; mt++)
                #pragma unroll
                for (int q = 0; q < QN; q++) {
                    mma16816(acc[mt][2 * q + 0], a[mt], b[q][0], b[q][1]);
                    mma16816(acc[mt][2 * q + 1], a[mt], b[q][2], b[q][3]);
                }
        }
    }

    // -------- epilogue (register accumulators)
    const int rBase = mStart + wm * 32 + (lane >> 2);
    const int cBase = nStart + wn * (BN / 2) + (lane & 3) * 2;

    float2 bias2[2 * QN];
    if (FUSED) {
        #pragma unroll
        for (int nt = 0; nt < 2 * QN; nt++)
            bias2[nt] = *(const float2*)(bias + cBase + nt * 8);
    }

    #pragma unroll
    for (int mt = 0; mt < 2; mt++) {
        #pragma unroll
        for (int rs = 0; rs < 2; rs++) {
            const int row = rBase + mt * 16 + rs * 8;
            float* op = out + (size_t)row * 1024;

            if (FUSED) {
                const int sv = smap[row];
                const int bb = row >> 12;                  // Lw = 4096
                const float* yrow = y2
                    + (size_t)(bb * Ssent + (sv < 0 ? 0 : sv)) * 1024;
                #pragma unroll
                for (int nt = 0; nt < 2 * QN; nt++) {
                    const int col = cBase + nt * 8;
                    float2 yv = make_float2(0.f, 0.f);
                    if (sv >= 0) yv = *(const float2*)(yrow + col);
                    float2 o;
                    o.x = fmaxf(acc[mt][nt][rs * 2 + 0] + bias2[nt].x + yv.x, 0.f);
                    o.y = fmaxf(acc[mt][nt][rs * 2 + 1] + bias2[nt].y + yv.y, 0.f);
                    *(float2*)(op + col) = o;
                }
            } else {
                #pragma unroll
                for (int nt = 0; nt < 2 * QN; nt++) {
                    const int col = cBase + nt * 8;
                    *(float2*)(op + col) =
                        make_float2(acc[mt][nt][rs * 2 + 0],
                                    acc[mt][nt][rs * 2 + 1]);
                }
            }
        }
    }
}

// ---------------------------------------------------------------- launch
extern "C" void kernel_launch(void* const* d_in, const int* in_sizes, int n_in,
                              void* d_out, int out_size)
{
    const float* words = (const float*)d_in[0];  // [8, 4096, 1024]
    const float* sents = (const float*)d_in[1];  // [8, 255, 1024]
    const float* W1w   = (const float*)d_in[2];  // [1024, 2048]
    const float* W1b   = (const float*)d_in[3];  // [1024]
    const int*   smap  = (const int*)d_in[4];    // [8, 4096]
    float*       out   = (float*)d_out;          // [8, 4096, 1024]

    void *pAw, *pWa, *pWb, *pSp, *pY2;
    cudaGetSymbolAddress(&pAw, g_Aw);
    cudaGetSymbolAddress(&pWa, g_Wa);
    cudaGetSymbolAddress(&pWb, g_Wb);
    cudaGetSymbolAddress(&pSp, g_Sp);
    cudaGetSymbolAddress(&pY2, g_Y2);

    constexpr int SM_MAIN = STAGES * (TILE_A + 128 * ROWB);   // 61440
    constexpr int SM_SENT = STAGES * (TILE_A + 64 * ROWB);    // 46080
    cudaFuncSetAttribute((const void*)gemm_f16<true, 4>,
                         cudaFuncAttributeMaxDynamicSharedMemorySize, SM_MAIN);
    cudaFuncSetAttribute((const void*)gemm_f16<false, 2>,
                         cudaFuncAttributeMaxDynamicSharedMemorySize, SM_SENT);

    // ---- fork: branch B (sentence chain) runs concurrently on s_sb
    cudaEventRecord(s_fork, 0);
    cudaStreamWaitEvent(s_sb, s_fork, 0);

    // branch B: W conversion + sentence conversion + sentence pre-GEMM
    cvtW_f16<<<Dm, 256, 0, s_sb>>>(W1w, (__half*)pWa, (__half*)pWb);
    cvt_bulk_f16<<<510, 256, 0, s_sb>>>((const float4*)sents, (uint2*)pSp);
    dim3 gridS(Dm / 64, 2048 / 128);             // 16 x 16
    gemm_f16<false, 2><<<gridS, 256, SM_SENT, s_sb>>>(
        (const __half*)pSp, (const __half*)pWb,
        nullptr, nullptr, nullptr, (float*)pY2);
    cudaEventRecord(s_join, s_sb);

    // branch A (default stream): words conversion (DRAM-bound, ~same duration)
    cvt_bulk_f16<<<8192, 256>>>((const float4*)words, (uint2*)pAw);

    // ---- join: main GEMM needs g_Aw (A), g_Wa (B) and g_Y2 (epilogue)
    cudaStreamWaitEvent(0, s_join, 0);

    dim3 gridM(Dm / 128, (Bsz * Lw) / 128);      // 8 x 256
    gemm_f16<true, 4><<<gridM, 256, SM_MAIN>>>(
        (const __half*)pAw, (const __half*)pWa,
        W1b, smap, (const float*)pY2, out);
}